// round 8
// baseline (speedup 1.0000x reference)
#include <cuda_runtime.h>
#include <cuda_bf16.h>
#include <math.h>
#include <stdint.h>

#define B_ROWS    8192
#define D_DIM     256
#define N_CLASSES 512
#define ALPHA     0.1
#define LIST_CAP  96        // max rows/class; Poisson(16) max ~45, big margin
#define NWARP     16        // warps per gather block (512 threads)

// Per-class row lists + counts (built by scatter, consumed+reset by gather).
__device__ uint16_t           g_list[N_CLASSES * LIST_CAP];
__device__ int                g_cnt[N_CLASSES];

// Column totals, one 128B line per float4 slot.
struct Pad128 { float4 v; float4 pad[7]; };
__device__ Pad128             g_T4p[D_DIM / 4];
__device__ double             g_ps;      // sum_c ||S_c||^2
__device__ unsigned long long g_np;      // sum_c count_c^2
__device__ unsigned int       g_ticket;

__device__ __forceinline__ void red_add_v4(float4* addr, float4 v) {
    asm volatile("red.global.add.v4.f32 [%0], {%1,%2,%3,%4};"
                 :: "l"(addr), "f"(v.x), "f"(v.y), "f"(v.z), "f"(v.w)
                 : "memory");
}

// acq_rel ticket: release publishes this block's device-scope REDs (ordered by
// the preceding __syncthreads); acquire in the last block makes all visible.
// No MEMBAR.GPU / L1 flush.
__device__ __forceinline__ unsigned ticket_acq_rel(unsigned int* a) {
    unsigned old;
    asm volatile("atom.add.acq_rel.gpu.global.u32 %0, [%1], 1;"
                 : "=r"(old) : "l"(a) : "memory");
    return old;
}

__device__ __forceinline__ float4 ldcg4(const float4* p) {
    float4 v;
    asm volatile("ld.global.cg.v4.f32 {%0,%1,%2,%3}, [%4];"
                 : "=f"(v.x), "=f"(v.y), "=f"(v.z), "=f"(v.w) : "l"(p));
    return v;
}

// ---------------------------------------------------------------------------
// Kernel 1: scatter rows into per-class lists. 32 blocks x 256 threads,
// one row per thread. 8192 atomics over 512 addresses (16/addr).
// ---------------------------------------------------------------------------
__global__ void scatter_kernel(const int* __restrict__ y_true) {
    const int r = blockIdx.x * 256 + threadIdx.x;
    const int c = y_true[r];
    const int pos = atomicAdd(&g_cnt[c], 1);
    if (pos < LIST_CAP) g_list[c * LIST_CAP + pos] = (uint16_t)r;
}

// ---------------------------------------------------------------------------
// Kernel 2: gather. One class per block, 512 blocks x 512 threads.
// NO label scan: reads its precomputed list. One row per warp (typical).
// ---------------------------------------------------------------------------
__global__ __launch_bounds__(512)
void gather_kernel(const float4* __restrict__ yp, float* __restrict__ out) {
    __shared__ uint16_t list[LIST_CAP];
    __shared__ int      cnt;
    __shared__ float4   wsum[NWARP][64];     // 16 KB
    __shared__ double   shP[64];
    __shared__ int      isLast;

    const int t    = threadIdx.x;
    const int w    = t >> 5;
    const int lane = t & 31;
    const int c    = blockIdx.x;             // my class

    if (t == 0) {
        cnt = g_cnt[c];
        g_cnt[c] = 0;                         // replay hygiene (only we touch it)
    }
    if (t < LIST_CAP) list[t] = g_list[c * LIST_CAP + t];  // entries >= cnt unused
    __syncthreads();

    const int n = min(cnt, LIST_CAP);

    // ---- gather: warp w handles rows w, w+16, ... (typically one) ----
    float4 A = make_float4(0.f, 0.f, 0.f, 0.f);
    float4 Bv = make_float4(0.f, 0.f, 0.f, 0.f);
    for (int j = w; j < n; j += NWARP) {
        const int r = list[j];
        float4 a = __ldcs(&yp[r * 64 + lane]);       // streaming: read-once
        float4 b = __ldcs(&yp[r * 64 + 32 + lane]);
        float sq = a.x*a.x + a.y*a.y + a.z*a.z + a.w*a.w
                 + b.x*b.x + b.y*b.y + b.z*b.z + b.w*b.w;
        #pragma unroll
        for (int o = 16; o > 0; o >>= 1)
            sq += __shfl_xor_sync(0xffffffffu, sq, o);
        const float inv = (sq > 0.0f) ? rsqrtf(sq) : 0.0f;
        A.x += a.x * inv; A.y += a.y * inv; A.z += a.z * inv; A.w += a.w * inv;
        Bv.x += b.x * inv; Bv.y += b.y * inv; Bv.z += b.z * inv; Bv.w += b.w * inv;
    }
    wsum[w][lane]      = A;
    wsum[w][32 + lane] = Bv;
    __syncthreads();

    // ---- combine 16 warp-partials; threads 0..63 own one float4 slot ----
    if (t < 64) {
        float4 S = wsum[0][t];
        #pragma unroll
        for (int i = 1; i < NWARP; i++) {
            float4 v = wsum[i][t];
            S.x += v.x; S.y += v.y; S.z += v.z; S.w += v.w;
        }
        red_add_v4(&g_T4p[t].v, S);          // T column partial (device RED)
        shP[t] = (double)S.x * S.x + (double)S.y * S.y
               + (double)S.z * S.z + (double)S.w * S.w;
    }
    __syncthreads();
    if (t < 32) {
        double p = shP[t] + shP[t + 32];
        #pragma unroll
        for (int o = 16; o > 0; o >>= 1)
            p += __shfl_xor_sync(0xffffffffu, p, o);
        if (t == 0) {
            atomicAdd(&g_ps, p);
            long long nn = n;
            atomicAdd(&g_np, (unsigned long long)(nn * nn));
        }
    }
    __syncthreads();                          // all REDs issued before release

    // ---- acq_rel ticket + epilogue ----
    if (t == 0)
        isLast = (ticket_acq_rel(&g_ticket) == gridDim.x - 1) ? 1 : 0;
    __syncthreads();

    if (isLast) {
        if (t < 64) {
            float4 T = ldcg4(&g_T4p[t].v);    // L2 read (where REDs landed)
            g_T4p[t].v = make_float4(0.f, 0.f, 0.f, 0.f);   // replay hygiene
            shP[t] = (double)T.x * T.x + (double)T.y * T.y
                   + (double)T.z * T.z + (double)T.w * T.w;
        }
        __syncthreads();
        if (t < 32) {
            double p = shP[t] + shP[t + 32];
            #pragma unroll
            for (int o = 16; o > 0; o >>= 1)
                p += __shfl_xor_sync(0xffffffffu, p, o);
            if (t == 0) {
                double pos_sum   = atomicAdd(&g_ps, 0.0);
                double n_pos     = (double)atomicAdd(&g_np, 0ull);
                g_ps = 0.0; g_np = 0ull; g_ticket = 0u;      // replay hygiene
                double total_sum = p;
                double n_neg   = (double)B_ROWS * (double)B_ROWS - n_pos;
                double neg_sum = total_sum - pos_sum;
                double pos_d   = pos_sum / n_pos;
                double neg_d   = (n_neg > 0.0) ? (neg_sum / n_neg) : 0.0;
                double r = pos_d - neg_d + ALPHA;
                out[0] = (float)(r > 0.0 ? r : 0.0);
            }
        }
    }
}

// ---------------------------------------------------------------------------
extern "C" void kernel_launch(void* const* d_in, const int* in_sizes, int n_in,
                              void* d_out, int out_size) {
    const int*   y_true;
    const float* y_pred;
    if (in_sizes[0] == B_ROWS) {
        y_true = (const int*)d_in[0];
        y_pred = (const float*)d_in[1];
    } else {
        y_true = (const int*)d_in[1];
        y_pred = (const float*)d_in[0];
    }
    float* out = (float*)d_out;

    scatter_kernel<<<B_ROWS / 256, 256>>>(y_true);
    gather_kernel<<<N_CLASSES, 512>>>((const float4*)y_pred, out);
}

// round 9
// speedup vs baseline: 1.1250x; 1.1250x over previous
#include <cuda_runtime.h>
#include <cuda_bf16.h>
#include <math.h>
#include <stdint.h>

#define B_ROWS    8192
#define D_DIM     256
#define N_CLASSES 512
#define ALPHA     0.1
#define LIST_CAP  96        // max rows/class; Poisson(16) max ~45, big margin
#define NWARP     16        // warps per block (512 threads)
#define NREP      8         // replicas of column-total accumulator

// Column totals: NREP replicas, one 128B line per float4 slot.
// RED chain per address = 512/NREP = 64 ops (~220 cyc) -- negligible.
struct Pad128 { float4 v; float4 pad[7]; };
__device__ Pad128       g_T4p[NREP][D_DIM / 4];
__device__ double2      g_rec[N_CLASSES];   // per-block {ps, n^2}: plain stores!
__device__ unsigned int g_ticket;

__device__ __forceinline__ void red_add_v4(float4* addr, float4 v) {
    asm volatile("red.global.add.v4.f32 [%0], {%1,%2,%3,%4};"
                 :: "l"(addr), "f"(v.x), "f"(v.y), "f"(v.z), "f"(v.w)
                 : "memory");
}

// acq_rel ticket: release publishes this block's prior stores/REDs; acquire in
// the last block makes all of them visible. No MEMBAR.GPU / L1 flush.
__device__ __forceinline__ unsigned ticket_acq_rel(unsigned int* a) {
    unsigned old;
    asm volatile("atom.add.acq_rel.gpu.global.u32 %0, [%1], 1;"
                 : "=r"(old) : "l"(a) : "memory");
    return old;
}

__device__ __forceinline__ float4 ldcg4(const float4* p) {
    float4 v;
    asm volatile("ld.global.cg.v4.f32 {%0,%1,%2,%3}, [%4];"
                 : "=f"(v.x), "=f"(v.y), "=f"(v.z), "=f"(v.w) : "l"(p));
    return v;
}
__device__ __forceinline__ double2 ldcg2d(const double2* p) {
    double2 v;
    asm volatile("ld.global.cg.v2.f64 {%0,%1}, [%2];"
                 : "=d"(v.x), "=d"(v.y) : "l"(p));
    return v;
}

// ---------------------------------------------------------------------------
// ONE kernel, one class per block. 512 blocks x 512 threads.
// ---------------------------------------------------------------------------
__global__ __launch_bounds__(512)
void triplet_kernel(const int4* __restrict__ y4,
                    const float4* __restrict__ yp,
                    float* __restrict__ out) {
    __shared__ uint16_t list[LIST_CAP];
    __shared__ int      cnt;
    __shared__ float4   wsum[NWARP][64];     // 16 KB
    __shared__ double   shA[64];
    __shared__ double   shB[16];
    __shared__ int      isLast;

    const int t    = threadIdx.x;
    const int w    = t >> 5;
    const int lane = t & 31;
    const int c    = blockIdx.x;             // my class

    if (t == 0) cnt = 0;
    __syncthreads();

    // ---- 1) label scan: 4 x int4 per thread (16 labels), L2-resident ----
    #pragma unroll
    for (int i = 0; i < (B_ROWS / 4) / 512; i++) {
        const int q = t + i * 512;           // int4 index
        const int4 L = y4[q];
        if (L.x == c) { int p = atomicAdd(&cnt, 1); if (p < LIST_CAP) list[p] = (uint16_t)(q * 4 + 0); }
        if (L.y == c) { int p = atomicAdd(&cnt, 1); if (p < LIST_CAP) list[p] = (uint16_t)(q * 4 + 1); }
        if (L.z == c) { int p = atomicAdd(&cnt, 1); if (p < LIST_CAP) list[p] = (uint16_t)(q * 4 + 2); }
        if (L.w == c) { int p = atomicAdd(&cnt, 1); if (p < LIST_CAP) list[p] = (uint16_t)(q * 4 + 3); }
    }
    __syncthreads();

    // ---- 2) gather: warp w handles rows w, w+16, ... (typically one) ----
    const int full_n = cnt;
    const int n = min(full_n, LIST_CAP);
    float4 A = make_float4(0.f, 0.f, 0.f, 0.f);
    float4 Bv = make_float4(0.f, 0.f, 0.f, 0.f);
    for (int j = w; j < n; j += NWARP) {
        const int r = list[j];
        float4 a = __ldcs(&yp[r * 64 + lane]);       // streaming: read-once
        float4 b = __ldcs(&yp[r * 64 + 32 + lane]);
        float sq = a.x*a.x + a.y*a.y + a.z*a.z + a.w*a.w
                 + b.x*b.x + b.y*b.y + b.z*b.z + b.w*b.w;
        #pragma unroll
        for (int o = 16; o > 0; o >>= 1)
            sq += __shfl_xor_sync(0xffffffffu, sq, o);
        const float inv = (sq > 0.0f) ? rsqrtf(sq) : 0.0f;
        A.x += a.x * inv; A.y += a.y * inv; A.z += a.z * inv; A.w += a.w * inv;
        Bv.x += b.x * inv; Bv.y += b.y * inv; Bv.z += b.z * inv; Bv.w += b.w * inv;
    }
    wsum[w][lane]      = A;
    wsum[w][32 + lane] = Bv;
    __syncthreads();

    // ---- 3) combine 16 warp-partials; threads 0..63 own one float4 slot ----
    if (t < 64) {
        float4 S = wsum[0][t];
        #pragma unroll
        for (int i = 1; i < NWARP; i++) {
            float4 v = wsum[i][t];
            S.x += v.x; S.y += v.y; S.z += v.z; S.w += v.w;
        }
        red_add_v4(&g_T4p[blockIdx.x & (NREP - 1)][t].v, S);   // spread REDs
        shA[t] = (double)S.x * S.x + (double)S.y * S.y
               + (double)S.z * S.z + (double)S.w * S.w;
    }
    __syncthreads();
    if (t < 32) {
        double p = shA[t] + shA[t + 32];
        #pragma unroll
        for (int o = 16; o > 0; o >>= 1)
            p += __shfl_xor_sync(0xffffffffu, p, o);
        if (t == 0) {
            // per-block record: PLAIN store, distinct address per block
            double nn = (double)full_n;
            g_rec[blockIdx.x] = make_double2(p, nn * nn);
        }
    }
    __syncthreads();                          // record + REDs before release

    // ---- 4) acq_rel ticket + epilogue ----
    if (t == 0)
        isLast = (ticket_acq_rel(&g_ticket) == gridDim.x - 1) ? 1 : 0;
    __syncthreads();

    if (isLast) {
        // (a) reduce 512 per-block records: one double2 per thread
        double2 rec = ldcg2d(&g_rec[t]);
        #pragma unroll
        for (int o = 16; o > 0; o >>= 1) {
            rec.x += __shfl_xor_sync(0xffffffffu, rec.x, o);
            rec.y += __shfl_xor_sync(0xffffffffu, rec.y, o);
        }
        if (lane == 0) { shA[w] = rec.x; shB[w] = rec.y; }

        // (b) column totals: threads 0..63 sum NREP replicas, zero them
        __syncthreads();
        double tot = 0.0;
        if (t < 64) {
            float4 T = make_float4(0.f, 0.f, 0.f, 0.f);
            #pragma unroll
            for (int r = 0; r < NREP; r++) {
                float4 v = ldcg4(&g_T4p[r][t].v);
                g_T4p[r][t].v = make_float4(0.f, 0.f, 0.f, 0.f); // replay hygiene
                T.x += v.x; T.y += v.y; T.z += v.z; T.w += v.w;
            }
            tot = (double)T.x * T.x + (double)T.y * T.y
                + (double)T.z * T.z + (double)T.w * T.w;
        }
        __syncthreads();
        double psum = (t < 16) ? shA[t] : 0.0;
        double nsum = (t < 16) ? shB[t] : 0.0;
        if (t < 64) shA[t] = tot;
        __syncthreads();

        if (t < 32) {
            double tt = shA[t] + shA[t + 32];
            #pragma unroll
            for (int o = 16; o > 0; o >>= 1) {
                tt   += __shfl_xor_sync(0xffffffffu, tt, o);
                psum += __shfl_xor_sync(0xffffffffu, psum, o);
                nsum += __shfl_xor_sync(0xffffffffu, nsum, o);
            }
            if (t == 0) {
                g_ticket = 0u;                               // replay hygiene
                double pos_sum   = psum;
                double n_pos     = nsum;
                double total_sum = tt;
                double n_neg   = (double)B_ROWS * (double)B_ROWS - n_pos;
                double neg_sum = total_sum - pos_sum;
                double pos_d   = pos_sum / n_pos;
                double neg_d   = (n_neg > 0.0) ? (neg_sum / n_neg) : 0.0;
                double r = pos_d - neg_d + ALPHA;
                out[0] = (float)(r > 0.0 ? r : 0.0);
            }
        }
    }
}

// ---------------------------------------------------------------------------
extern "C" void kernel_launch(void* const* d_in, const int* in_sizes, int n_in,
                              void* d_out, int out_size) {
    const int*   y_true;
    const float* y_pred;
    if (in_sizes[0] == B_ROWS) {
        y_true = (const int*)d_in[0];
        y_pred = (const float*)d_in[1];
    } else {
        y_true = (const int*)d_in[1];
        y_pred = (const float*)d_in[0];
    }
    float* out = (float*)d_out;

    triplet_kernel<<<N_CLASSES, 512>>>((const int4*)y_true,
                                       (const float4*)y_pred, out);
}

// round 10
// speedup vs baseline: 1.2774x; 1.1355x over previous
#include <cuda_runtime.h>
#include <cuda_bf16.h>
#include <math.h>
#include <stdint.h>

#define B_ROWS    8192
#define D_DIM     256
#define N_CLASSES 512
#define ALPHA     0.1
#define R_REP     4
#define SLOTS     (N_CLASSES * (D_DIM / 4))   // 32768 float4 slots per replica
#define RBLK      128                          // reduce grid

// Scratch (zero-init at load; every consumer re-zeroes -> replay-clean).
__device__ float4       g_cs4[R_REP * SLOTS];  // class sums [rep][class][col4], 2MB
__device__ int          g_cnt[N_CLASSES];
struct Pad128 { float4 v; float4 pad[7]; };
__device__ Pad128       g_T4p[R_REP][D_DIM / 4];  // padded, replicated col totals
__device__ double       g_rec[RBLK];           // per-block ps partials: plain stores
__device__ unsigned int g_ticket;

__device__ __forceinline__ void red_add_v4(float4* addr, float4 v) {
    asm volatile("red.global.add.v4.f32 [%0], {%1,%2,%3,%4};"
                 :: "l"(addr), "f"(v.x), "f"(v.y), "f"(v.z), "f"(v.w)
                 : "memory");
}
// acq_rel ticket: no MEMBAR.GPU, no CCTL.IVALL.
__device__ __forceinline__ unsigned ticket_acq_rel(unsigned int* a) {
    unsigned old;
    asm volatile("atom.add.acq_rel.gpu.global.u32 %0, [%1], 1;"
                 : "=r"(old) : "l"(a) : "memory");
    return old;
}
__device__ __forceinline__ float4 ldcg4(const float4* p) {
    float4 v;
    asm volatile("ld.global.cg.v4.f32 {%0,%1,%2,%3}, [%4];"
                 : "=f"(v.x), "=f"(v.y), "=f"(v.z), "=f"(v.w) : "l"(p));
    return v;
}
__device__ __forceinline__ double ldcgd(const double* p) {
    double v;
    asm volatile("ld.global.cg.f64 %0, [%1];" : "=d"(v) : "l"(p));
    return v;
}

// ---------------------------------------------------------------------------
// Kernel 1 (R3-proven shape, 5.7us): 4 rows / 256-thread block, 2048 blocks.
// 64 threads per row, one float4 each; normalize; v4-RED into replica bid&3.
// ---------------------------------------------------------------------------
__global__ void accum_kernel(const int* __restrict__ y_true,
                             const float4* __restrict__ yp4) {
    const int tid    = threadIdx.x;
    const int sub    = tid >> 6;
    const int lane64 = tid & 63;
    const int row    = blockIdx.x * 4 + sub;
    const int rep    = blockIdx.x & (R_REP - 1);

    float4 v = yp4[row * 64 + lane64];
    float sq = v.x*v.x + v.y*v.y + v.z*v.z + v.w*v.w;
    #pragma unroll
    for (int o = 16; o > 0; o >>= 1)
        sq += __shfl_xor_sync(0xffffffffu, sq, o);

    __shared__ float sh_warp[8];
    if ((tid & 31) == 0) sh_warp[tid >> 5] = sq;
    __syncthreads();
    const float norm2 = sh_warp[sub * 2] + sh_warp[sub * 2 + 1];
    const float inv = (norm2 > 0.0f) ? rsqrtf(norm2) : 0.0f;

    const int c = __ldg(&y_true[row]);
    v.x *= inv; v.y *= inv; v.z *= inv; v.w *= inv;
    red_add_v4(&g_cs4[(rep * N_CLASSES + c) * 64 + lane64], v);
    if (lane64 == 0) atomicAdd(&g_cnt[c], 1);
}

// ---------------------------------------------------------------------------
// Kernel 2: reduce + finalize. 128 blocks x 256 threads (one wave, low regs).
// Thread owns slot = bid*256+t: 4 coalesced replica loads (L2 hits), zero them,
// ps partial; padded+replicated T REDs (<=32 ops/address); plain-store record;
// acq_rel ticket; last block: tiny epilogue.
// ---------------------------------------------------------------------------
__global__ __launch_bounds__(256)
void reduce_final_kernel(float* __restrict__ out) {
    const int t    = threadIdx.x;
    const int slot = blockIdx.x * 256 + t;      // 0..32767
    const int col  = slot & 63;

    float4 S = make_float4(0.f, 0.f, 0.f, 0.f);
    #pragma unroll
    for (int r = 0; r < R_REP; r++) {
        const int idx = r * SLOTS + slot;       // coalesced within each replica
        float4 v = g_cs4[idx];
        g_cs4[idx] = make_float4(0.f, 0.f, 0.f, 0.f);   // replay hygiene
        S.x += v.x; S.y += v.y; S.z += v.z; S.w += v.w;
    }
    double ps = (double)S.x * S.x + (double)S.y * S.y
              + (double)S.z * S.z + (double)S.w * S.w;
    red_add_v4(&g_T4p[blockIdx.x & (R_REP - 1)][col].v, S);

    __shared__ double shA[256];
    shA[t] = ps;
    __syncthreads();
    #pragma unroll
    for (int off = 128; off > 0; off >>= 1) {
        if (t < off) shA[t] += shA[t + off];
        __syncthreads();
    }
    if (t == 0) g_rec[blockIdx.x] = shA[0];     // plain store, distinct address
    __syncthreads();                            // order everything before release

    __shared__ int isLast;
    if (t == 0)
        isLast = (ticket_acq_rel(&g_ticket) == gridDim.x - 1) ? 1 : 0;
    __syncthreads();
    if (!isLast) return;

    // ---- epilogue (one block) ----
    double pr = (t < RBLK) ? ldcgd(&g_rec[t]) : 0.0;

    double tot = 0.0;
    if (t < 64) {
        float4 T = make_float4(0.f, 0.f, 0.f, 0.f);
        #pragma unroll
        for (int r = 0; r < R_REP; r++) {
            float4 v = ldcg4(&g_T4p[r][t].v);
            g_T4p[r][t].v = make_float4(0.f, 0.f, 0.f, 0.f);  // replay hygiene
            T.x += v.x; T.y += v.y; T.z += v.z; T.w += v.w;
        }
        tot = (double)T.x * T.x + (double)T.y * T.y
            + (double)T.z * T.z + (double)T.w * T.w;
    }

    long long c0 = g_cnt[t];        g_cnt[t] = 0;
    long long c1 = g_cnt[t + 256];  g_cnt[t + 256] = 0;
    double np = (double)(c0 * c0 + c1 * c1);

    __shared__ double shB[256], shC[256];
    shA[t] = pr; shB[t] = tot; shC[t] = np;
    __syncthreads();
    #pragma unroll
    for (int off = 128; off > 0; off >>= 1) {
        if (t < off) {
            shA[t] += shA[t + off];
            shB[t] += shB[t + off];
            shC[t] += shC[t + off];
        }
        __syncthreads();
    }

    if (t == 0) {
        g_ticket = 0u;                          // replay hygiene
        double pos_sum   = shA[0];
        double total_sum = shB[0];
        double n_pos     = shC[0];
        double n_neg   = (double)B_ROWS * (double)B_ROWS - n_pos;
        double neg_sum = total_sum - pos_sum;
        double pos_d   = pos_sum / n_pos;
        double neg_d   = (n_neg > 0.0) ? (neg_sum / n_neg) : 0.0;
        double r = pos_d - neg_d + ALPHA;
        out[0] = (float)(r > 0.0 ? r : 0.0);
    }
}

// ---------------------------------------------------------------------------
extern "C" void kernel_launch(void* const* d_in, const int* in_sizes, int n_in,
                              void* d_out, int out_size) {
    const int*   y_true;
    const float* y_pred;
    if (in_sizes[0] == B_ROWS) {
        y_true = (const int*)d_in[0];
        y_pred = (const float*)d_in[1];
    } else {
        y_true = (const int*)d_in[1];
        y_pred = (const float*)d_in[0];
    }
    float* out = (float*)d_out;

    accum_kernel<<<B_ROWS / 4, 256>>>(y_true, (const float4*)y_pred);
    reduce_final_kernel<<<RBLK, 256>>>(out);
}

// round 12
// speedup vs baseline: 1.4850x; 1.1625x over previous
#include <cuda_runtime.h>
#include <cuda_bf16.h>
#include <math.h>
#include <stdint.h>

#define B_ROWS    8192
#define D_DIM     256
#define N_CLASSES 512
#define ALPHA     0.1
#define LIST_CAP  96        // max rows/class; Poisson(16) max ~45, big margin
#define NWARP     16        // warps per block (512 threads)
#define NREP      4         // replicas of column-total accumulator

// Column totals: NREP replicas, one 128B line per float4 slot (chain <=128).
struct Pad128 { float4 v; float4 pad[7]; };
__device__ Pad128       g_T4p[NREP][D_DIM / 4];
__device__ double       g_recP[N_CLASSES];   // per-block ps partial (plain store)
__device__ double       g_recN[N_CLASSES];   // per-block n^2      (plain store)
__device__ unsigned int g_ticket;

__device__ __forceinline__ void red_add_v4(float4* addr, float4 v) {
    asm volatile("red.global.add.v4.f32 [%0], {%1,%2,%3,%4};"
                 :: "l"(addr), "f"(v.x), "f"(v.y), "f"(v.z), "f"(v.w)
                 : "memory");
}
// acq_rel ticket: release publishes this block's prior (syncthreads-ordered)
// stores/REDs; acquire in the last block makes all blocks' visible.
// No MEMBAR.GPU, no CCTL.IVALL (L1 flush).
__device__ __forceinline__ unsigned ticket_acq_rel(unsigned int* a) {
    unsigned old;
    asm volatile("atom.add.acq_rel.gpu.global.u32 %0, [%1], 1;"
                 : "=r"(old) : "l"(a) : "memory");
    return old;
}
__device__ __forceinline__ float4 ldcg4(const float4* p) {
    float4 v;
    asm volatile("ld.global.cg.v4.f32 {%0,%1,%2,%3}, [%4];"
                 : "=f"(v.x), "=f"(v.y), "=f"(v.z), "=f"(v.w) : "l"(p));
    return v;
}
__device__ __forceinline__ double ldcgd(const double* p) {
    double v;
    asm volatile("ld.global.cg.f64 %0, [%1];" : "=d"(v) : "l"(p));
    return v;
}

// ---------------------------------------------------------------------------
// ONE kernel, one class per block. 512 blocks x 512 threads, ONE wave (4/SM).
// ---------------------------------------------------------------------------
__global__ __launch_bounds__(512, 4)
void triplet_kernel(const int4* __restrict__ y4,
                    const float4* __restrict__ yp,
                    float* __restrict__ out) {
    __shared__ uint16_t list[LIST_CAP];
    __shared__ int      cnt;
    __shared__ float4   wsum[NWARP][64];     // 16 KB
    __shared__ double   shA[512];            // 4 KB
    __shared__ double   shB[512];            // 4 KB (epilogue)
    __shared__ double   shC[512];            // 4 KB (epilogue)
    __shared__ int      isLast;

    const int t    = threadIdx.x;
    const int w    = t >> 5;
    const int lane = t & 31;
    const int c    = blockIdx.x;             // my class

    if (t == 0) cnt = 0;
    __syncthreads();

    // ---- 1) label scan: 4 x int4 per thread (16 labels), L2-resident ----
    #pragma unroll
    for (int i = 0; i < (B_ROWS / 4) / 512; i++) {
        const int q = t + i * 512;           // int4 index
        const int4 L = y4[q];
        if (L.x == c) { int p = atomicAdd(&cnt, 1); if (p < LIST_CAP) list[p] = (uint16_t)(q * 4 + 0); }
        if (L.y == c) { int p = atomicAdd(&cnt, 1); if (p < LIST_CAP) list[p] = (uint16_t)(q * 4 + 1); }
        if (L.z == c) { int p = atomicAdd(&cnt, 1); if (p < LIST_CAP) list[p] = (uint16_t)(q * 4 + 2); }
        if (L.w == c) { int p = atomicAdd(&cnt, 1); if (p < LIST_CAP) list[p] = (uint16_t)(q * 4 + 3); }
    }
    __syncthreads();

    // ---- 2) gather: warp w handles rows w, w+16, ... (typically one) ----
    const int full_n = cnt;
    const int n = min(full_n, LIST_CAP);
    float4 A = make_float4(0.f, 0.f, 0.f, 0.f);
    float4 Bv = make_float4(0.f, 0.f, 0.f, 0.f);
    for (int j = w; j < n; j += NWARP) {
        const int r = list[j];
        float4 a = __ldcs(&yp[r * 64 + lane]);       // streaming: read-once
        float4 b = __ldcs(&yp[r * 64 + 32 + lane]);
        float sq = a.x*a.x + a.y*a.y + a.z*a.z + a.w*a.w
                 + b.x*b.x + b.y*b.y + b.z*b.z + b.w*b.w;
        #pragma unroll
        for (int o = 16; o > 0; o >>= 1)
            sq += __shfl_xor_sync(0xffffffffu, sq, o);
        const float inv = (sq > 0.0f) ? rsqrtf(sq) : 0.0f;
        A.x += a.x * inv; A.y += a.y * inv; A.z += a.z * inv; A.w += a.w * inv;
        Bv.x += b.x * inv; Bv.y += b.y * inv; Bv.z += b.z * inv; Bv.w += b.w * inv;
    }
    wsum[w][lane]      = A;
    wsum[w][32 + lane] = Bv;
    __syncthreads();

    // ---- 3) combine 16 warp-partials; threads 0..63 own one float4 slot ----
    if (t < 64) {
        float4 S = wsum[0][t];
        #pragma unroll
        for (int i = 1; i < NWARP; i++) {
            float4 v = wsum[i][t];
            S.x += v.x; S.y += v.y; S.z += v.z; S.w += v.w;
        }
        red_add_v4(&g_T4p[blockIdx.x & (NREP - 1)][t].v, S);   // spread REDs
        shA[t] = (double)S.x * S.x + (double)S.y * S.y
               + (double)S.z * S.z + (double)S.w * S.w;
    }
    __syncthreads();
    if (t < 32) {
        double p = shA[t] + shA[t + 32];
        #pragma unroll
        for (int o = 16; o > 0; o >>= 1)
            p += __shfl_xor_sync(0xffffffffu, p, o);
        if (t == 0) {
            // per-block records: PLAIN stores to distinct addresses (no chains)
            double nn = (double)full_n;
            g_recP[blockIdx.x] = p;
            g_recN[blockIdx.x] = nn * nn;
        }
    }
    __syncthreads();                          // records + REDs before release

    // ---- 4) acq_rel ticket + epilogue (no membar, no L1 flush) ----
    if (t == 0)
        isLast = (ticket_acq_rel(&g_ticket) == gridDim.x - 1) ? 1 : 0;
    __syncthreads();

    if (isLast) {
        // records: thread t folds exactly record t (512 threads, 512 records).
        // ld.cg -- this block's own record store may sit in its L1.
        double pr = ldcgd(&g_recP[t]);
        double nr = ldcgd(&g_recN[t]);

        // column totals: threads 0..63 sum NREP replicas, zero them
        double tot = 0.0;
        if (t < 64) {
            float4 T = make_float4(0.f, 0.f, 0.f, 0.f);
            #pragma unroll
            for (int r = 0; r < NREP; r++) {
                float4 v = ldcg4(&g_T4p[r][t].v);
                g_T4p[r][t].v = make_float4(0.f, 0.f, 0.f, 0.f);  // replay hygiene
                T.x += v.x; T.y += v.y; T.z += v.z; T.w += v.w;
            }
            tot = (double)T.x * T.x + (double)T.y * T.y
                + (double)T.z * T.z + (double)T.w * T.w;
        }

        shA[t] = pr; shB[t] = nr; shC[t] = tot;
        __syncthreads();
        #pragma unroll
        for (int off = 256; off > 0; off >>= 1) {
            if (t < off) {
                shA[t] += shA[t + off];
                shB[t] += shB[t + off];
                shC[t] += shC[t + off];
            }
            __syncthreads();
        }

        if (t == 0) {
            g_ticket = 0u;                   // replay hygiene
            double pos_sum   = shA[0];
            double n_pos     = shB[0];
            double total_sum = shC[0];
            double n_neg   = (double)B_ROWS * (double)B_ROWS - n_pos;
            double neg_sum = total_sum - pos_sum;
            double pos_d   = pos_sum / n_pos;
            double neg_d   = (n_neg > 0.0) ? (neg_sum / n_neg) : 0.0;
            double r = pos_d - neg_d + ALPHA;
            out[0] = (float)(r > 0.0 ? r : 0.0);
        }
    }
}

// ---------------------------------------------------------------------------
extern "C" void kernel_launch(void* const* d_in, const int* in_sizes, int n_in,
                              void* d_out, int out_size) {
    const int*   y_true;
    const float* y_pred;
    if (in_sizes[0] == B_ROWS) {
        y_true = (const int*)d_in[0];
        y_pred = (const float*)d_in[1];
    } else {
        y_true = (const int*)d_in[1];
        y_pred = (const float*)d_in[0];
    }
    float* out = (float*)d_out;

    triplet_kernel<<<N_CLASSES, 512>>>((const int4*)y_true,
                                       (const float4*)y_pred, out);
}